// round 15
// baseline (speedup 1.0000x reference)
#include <cuda_runtime.h>
#include <cstdint>

// ---- problem constants ----
#define NODES     4096
#define T_HIST    24
#define D_SKIP    256
#define E_END     128
#define KW        13
#define F_STEPS   12
#define OUT_DIM   2
#define NPB       5
#define NTHREADS  512
#define MAXCTA    832

// ---- smem layout (floats), occupancy-2 budget ----
// mainloop: xb 2 bufs x [128][68] @0 (quarters; converted in place per-quarter; ends 17408)
//           w1s 2 bufs x 4096 (fragment-order chunk) @17408 (ends 25600)
// stage 2 : hs [120][129] @0 (ends 15479), w2s [13][257] @15480 (ends 18821), red @18821
#define XB_OFF     0
#define XB_BUF     8704
#define XB_STRIDE  68
#define W1S_OFF    17408
#define W1S_BUF    4096
#define HS_OFF     0
#define HS_STRIDE  129
#define W2S_OFF    15480
#define W2S_STRIDE 257
#define RED_OFF    18821
#define SMEM_FLOATS 25600
#define SMEM_BYTES  (SMEM_FLOATS * 4)

// ---- device scratch ----
__device__ int d_perm[NODES];
__device__ int d_cta_expert[MAXCTA];
__device__ int d_cta_base[MAXCTA];
__device__ int d_cta_cnt[MAXCTA];
__device__ int d_num_ctas;
// W1 fragment order for 512-thread map:
// [ex][chunk c (8)][fragpos=kt*2+mt (8)][wq (4)][lane (32)][j (4)], tf32
__device__ float d_w1f[8 * E_END * D_SKIP];
__device__ float d_w2t[8 * KW * OUT_DIM * E_END]; // W2 transposed to [e][kk][o*128+en]

__device__ __forceinline__ float tf32_rna(float x) {
    unsigned u;
    asm("cvt.rna.tf32.f32 %0, %1;" : "=r"(u) : "f"(x));
    return __uint_as_float(u);
}
__device__ __forceinline__ void cp16(uint32_t dst, const float* src) {
    asm volatile("cp.async.ca.shared.global [%0], [%1], 16;" :: "r"(dst), "l"(src));
}

__device__ __forceinline__ void mma_tf32(float (&d)[4], const unsigned (&a)[4],
                                         unsigned b0, unsigned b1) {
    asm volatile(
        "mma.sync.aligned.m16n8k8.row.col.f32.tf32.tf32.f32 "
        "{%0,%1,%2,%3}, {%4,%5,%6,%7}, {%8,%9}, {%0,%1,%2,%3};"
        : "+f"(d[0]), "+f"(d[1]), "+f"(d[2]), "+f"(d[3])
        : "r"(a[0]), "r"(a[1]), "r"(a[2]), "r"(a[3]), "r"(b0), "r"(b1));
}

// ================= setup: block 0 = prepass, blocks 1.. = weight convert =================
__global__ void setup_kernel(const int* __restrict__ labels,
                             const float* __restrict__ W1,
                             const float* __restrict__ W2) {
    const int nt = blockDim.x;
    if (blockIdx.x == 0) {
        __shared__ int cnt[8], off[8], pos[8], blkoff[9], total_s;
        const int tid = threadIdx.x;
        const int lane = tid & 31;
        if (tid < 8) { cnt[tid] = 0; pos[tid] = 0; }
        __syncthreads();
        for (int i = tid; i < NODES; i += nt) {
            int l = labels[i];
            unsigned mask = __match_any_sync(0xffffffffu, l);
            int leader = __ffs(mask) - 1;
            if (lane == leader) atomicAdd(&cnt[l], __popc(mask));
        }
        __syncthreads();
        if (tid == 0) {
            int acc = 0, bacc = 0;
            for (int e = 0; e < 8; ++e) {
                off[e] = acc;
                blkoff[e] = bacc;
                acc += cnt[e];
                bacc += (cnt[e] + NPB - 1) / NPB;
            }
            blkoff[8] = bacc;
            total_s = bacc;
            d_num_ctas = bacc;
        }
        __syncthreads();
        for (int i = tid; i < NODES; i += nt) {
            int l = labels[i];
            unsigned mask = __match_any_sync(0xffffffffu, l);
            int leader = __ffs(mask) - 1;
            int rank = __popc(mask & ((1u << lane) - 1u));
            int basep = 0;
            if (lane == leader) basep = atomicAdd(&pos[l], __popc(mask));
            basep = __shfl_sync(0xffffffffu, basep, leader);
            d_perm[off[l] + basep + rank] = i;
        }
        const int total = total_s;
        for (int i = tid; i < total; i += nt) {
            int e = 0;
            while (blkoff[e + 1] <= i) ++e;
            int j = i - blkoff[e];
            int rem = cnt[e] - j * NPB;
            d_cta_expert[i] = e;
            d_cta_base[i]   = off[e] + j * NPB;
            d_cta_cnt[i]    = rem < NPB ? rem : NPB;
        }
    } else {
        const int idx = (blockIdx.x - 1) * nt + threadIdx.x;
        const int stride = (gridDim.x - 1) * nt;
        // W1 -> fragment-order tf32 (512-thread map)
        for (int i = idx; i < 8 * E_END * D_SKIP; i += stride) {
            int ex = i >> 15;
            int r  = i & 32767;
            int c  = r >> 12;
            int r2 = r & 4095;
            int fragpos = r2 >> 9;          // kt*2 + mt
            int wq  = (r2 >> 7) & 3;
            int lane2 = (r2 >> 2) & 31;
            int j   = r2 & 3;
            int kt = fragpos >> 1, mt = fragpos & 1;
            int g = lane2 >> 2, tig = lane2 & 3;
            int e = wq * 32 + mt * 16 + g + (j & 1) * 8;
            int k = c * 32 + kt * 8 + tig + (j >> 1) * 4;
            d_w1f[i] = tf32_rna(W1[(ex * E_END + e) * D_SKIP + k]);
        }
        for (int i = idx; i < 8 * KW * OUT_DIM * E_END; i += stride) {
            int e  = i / (KW * OUT_DIM * E_END);
            int r  = i - e * (KW * OUT_DIM * E_END);
            int kk = r >> 8;
            int oe = r & 255;
            int o  = oe >> 7;
            int en = oe & 127;
            d_w2t[i] = W2[((e * OUT_DIM + o) * E_END + en) * KW + kk];
        }
    }
}

// ================= main kernel =================
__global__ void __launch_bounds__(NTHREADS, 2)
tcnn_grouped_kernel(const float* __restrict__ x,
                    const float* __restrict__ b1,
                    const float* __restrict__ b2,
                    float* __restrict__ out)
{
    extern __shared__ __align__(16) float sm[];
    const int bid = blockIdx.x;
    if (bid >= d_num_ctas) return;

    const int expert = d_cta_expert[bid];
    const int nbase  = d_cta_base[bid];
    const int nm     = d_cta_cnt[bid];

    const int tid  = threadIdx.x;
    const int warp = tid >> 5;       // 0..15
    const int lane = tid & 31;
    const int g    = lane >> 2;
    const int tig  = lane & 3;
    const int wq   = warp & 3;       // 0..3 : e-quarter (32 each)
    const int wn   = warp >> 2;      // 0..3 : row-quarter (32 each)

    // per-node x base pointers
    const float* pxn[NPB];
    #pragma unroll
    for (int s = 0; s < NPB; ++s) {
        int node = (s < nm) ? d_perm[nbase + s] : d_perm[nbase];
        pxn[s] = x + (size_t)node * (T_HIST * D_SKIP);
    }

    const uint32_t smem_saddr = (uint32_t)__cvta_generic_to_shared(sm);
    const int xcount = nm * 384;      // cp16 ops per quarter (24t x 16q per node)

    // ---- issue xs quarter 0 into xbuf 0 ----
    {
        #pragma unroll 1
        for (int i = tid; i < xcount; i += NTHREADS) {
            int s = i / 384;
            int r = i - s * 384;
            int t = r >> 4;
            int qd = r & 15;
            cp16(smem_saddr + (((s * 24 + t) * XB_STRIDE + qd * 4) << 2),
                 pxn[s] + t * D_SKIP + qd * 4);
        }
        asm volatile("cp.async.commit_group;");
    }

    // ---- W1 fragment-order prefetch (register double-buffer) ----
    const float4* w1src4 = (const float4*)(d_w1f + (size_t)expert * (E_END * D_SKIP));
    float4* w1dst4base = (float4*)(sm + W1S_OFF);

    float4 pre[2];
    #pragma unroll
    for (int j = 0; j < 2; ++j)
        pre[j] = w1src4[tid + 512 * j];

    // ---- mainloop: D[e][row] = sum_k W1[e][k]*relu(x)[row][k] (tf32 mma) ----
    float acc[2][4][4];
    #pragma unroll
    for (int mt = 0; mt < 2; ++mt)
        #pragma unroll
        for (int nt = 0; nt < 4; ++nt)
            #pragma unroll
            for (int i = 0; i < 4; ++i) acc[mt][nt][i] = 0.f;

    const int aoff = wq * 32 + lane;   // float4 index within fragpos group

    #pragma unroll 1
    for (int c = 0; c < 8; ++c) {
        const int buf = c & 1;
        float* xbuf = sm + XB_OFF + ((c >> 1) & 1) * XB_BUF;

        // convert-pass scheduling:
        //  c==0           : wait q0, convert buf0 (own elements; published by barrier c=0)
        //  c odd, c<7     : wait q=(c+1)/2, convert its buffer (published by barrier c+1)
        if (c == 0 || ((c & 1) && c < 7)) {
            asm volatile("cp.async.wait_group 0;");
            float* cbuf = sm + XB_OFF + (((c + 1) >> 1) & 1) * XB_BUF;
            #pragma unroll 1
            for (int i = tid; i < xcount; i += NTHREADS) {
                int s = i / 384;
                int r = i - s * 384;
                int t = r >> 4;
                int qd = r & 15;
                float4* p = (float4*)(cbuf + (s * 24 + t) * XB_STRIDE + qd * 4);
                float4 v = *p;
                v.x = tf32_rna(fmaxf(v.x, 0.f));
                v.y = tf32_rna(fmaxf(v.y, 0.f));
                v.z = tf32_rna(fmaxf(v.z, 0.f));
                v.w = tf32_rna(fmaxf(v.w, 0.f));
                *p = v;
            }
        }

        // STS prefetched W1 chunk c (safe: mma c-1 reads other buf; c-2 readers flushed)
        {
            float4* dst = w1dst4base + buf * (W1S_BUF / 4);
            #pragma unroll
            for (int j = 0; j < 2; ++j)
                dst[tid + 512 * j] = pre[j];
        }
        if (c < 7) {
            const float4* src = w1src4 + (c + 1) * (W1S_BUF / 4);
            #pragma unroll
            for (int j = 0; j < 2; ++j)
                pre[j] = src[tid + 512 * j];
        }
        __syncthreads();   // w1s chunk c + converted quarter visible; prev mma done

        // issue xs quarter q+1 (post-barrier: quarter q-1 readers flushed)
        if ((c & 1) == 0 && c < 6) {
            const int qn = (c >> 1) + 1;
            const uint32_t dstb = smem_saddr + (qn & 1) * (XB_BUF * 4);
            const int kb4 = qn * 64;
            #pragma unroll 1
            for (int i = tid; i < xcount; i += NTHREADS) {
                int s = i / 384;
                int r = i - s * 384;
                int t = r >> 4;
                int qd = r & 15;
                cp16(dstb + (((s * 24 + t) * XB_STRIDE + qd * 4) << 2),
                     pxn[s] + kb4 + t * D_SKIP + qd * 4);
            }
            asm volatile("cp.async.commit_group;");
        }

        const float4* w1b4 = (const float4*)(sm + W1S_OFF + buf * W1S_BUF);
        #pragma unroll
        for (int kt = 0; kt < 4; ++kt) {
            const int xk = (c & 1) * 32 + kt * 8;  // k within quarter (xb)
            unsigned a[2][4];
            #pragma unroll
            for (int mt = 0; mt < 2; ++mt) {
                float4 av = w1b4[(kt * 2 + mt) * 128 + aoff];
                a[mt][0] = __float_as_uint(av.x);
                a[mt][1] = __float_as_uint(av.y);
                a[mt][2] = __float_as_uint(av.z);
                a[mt][3] = __float_as_uint(av.w);
            }
            #pragma unroll
            for (int nt = 0; nt < 4; ++nt) {
                const int col = wn * 32 + nt * 8 + g;   // row index
                unsigned b0  = __float_as_uint(xbuf[col * XB_STRIDE + xk + tig]);
                unsigned b1v = __float_as_uint(xbuf[col * XB_STRIDE + xk + tig + 4]);
                #pragma unroll
                for (int mt = 0; mt < 2; ++mt)
                    mma_tf32(acc[mt][nt], a[mt], b0, b1v);
            }
        }
    }

    __syncthreads();   // all xb/w1s reads done -> reuse as hs[row][e]

    // ---- stage-2 weights: contiguous copy from pre-transposed d_w2t ----
    {
        const float* w2g = d_w2t + expert * (KW * OUT_DIM * E_END);
        #pragma unroll
        for (int i = tid; i < KW * OUT_DIM * E_END; i += NTHREADS)
            sm[W2S_OFF + (i >> 8) * W2S_STRIDE + (i & 255)] = w2g[i];
    }

    // ---- epilogue: hs[row][e] = relu(D[e][row] + b1[e]) ----
    const float* b1g = b1 + expert * E_END;
    const int maxrow = nm * T_HIST;
    #pragma unroll
    for (int mt = 0; mt < 2; ++mt) {
        const int eA = wq * 32 + mt * 16 + g;
        const int eB = eA + 8;
        const float bA = b1g[eA];
        const float bB = b1g[eB];
        #pragma unroll
        for (int nt = 0; nt < 4; ++nt) {
            const int row0 = wn * 32 + nt * 8 + 2 * tig;
            if (row0 < maxrow) {
                sm[HS_OFF + row0 * HS_STRIDE + eA] = fmaxf(acc[mt][nt][0] + bA, 0.f);
                sm[HS_OFF + row0 * HS_STRIDE + eB] = fmaxf(acc[mt][nt][2] + bB, 0.f);
            }
            const int row1 = row0 + 1;
            if (row1 < maxrow) {
                sm[HS_OFF + row1 * HS_STRIDE + eA] = fmaxf(acc[mt][nt][1] + bA, 0.f);
                sm[HS_OFF + row1 * HS_STRIDE + eB] = fmaxf(acc[mt][nt][3] + bB, 0.f);
            }
        }
    }
    __syncthreads();

    // ---- stage 2: per-node temporal conv, register resident (16 warps, 2 rounds) ----
    #pragma unroll 1
    for (int iter = 0; iter < 2; ++iter) {
        const int wj   = iter * 16 + warp;
        const int node = wj >> 2;
        const int w4   = wj & 3;
        if (node < nm) {
            const int e = w4 * 32 + lane;
            float w2r[OUT_DIM][KW];
            #pragma unroll
            for (int o = 0; o < OUT_DIM; ++o)
                #pragma unroll
                for (int kk = 0; kk < KW; ++kk)
                    w2r[o][kk] = sm[W2S_OFF + kk * W2S_STRIDE + o * E_END + e];

            float a2[F_STEPS][OUT_DIM];
            #pragma unroll
            for (int f = 0; f < F_STEPS; ++f) { a2[f][0] = 0.f; a2[f][1] = 0.f; }

            const float* hsp = sm + HS_OFF + node * T_HIST * HS_STRIDE + e;
            #pragma unroll
            for (int t = 0; t < T_HIST; ++t) {
                const float hv = hsp[t * HS_STRIDE];
                #pragma unroll
                for (int kk = 0; kk < KW; ++kk) {
                    const int f = t - kk;
                    if (f >= 0 && f < F_STEPS) {
                        a2[f][0] = fmaf(hv, w2r[0][kk], a2[f][0]);
                        a2[f][1] = fmaf(hv, w2r[1][kk], a2[f][1]);
                    }
                }
            }
            #pragma unroll
            for (int f = 0; f < F_STEPS; ++f)
                #pragma unroll
                for (int o = 0; o < OUT_DIM; ++o) {
                    float v = a2[f][o];
                    v += __shfl_xor_sync(0xffffffffu, v, 16);
                    v += __shfl_xor_sync(0xffffffffu, v, 8);
                    v += __shfl_xor_sync(0xffffffffu, v, 4);
                    v += __shfl_xor_sync(0xffffffffu, v, 2);
                    v += __shfl_xor_sync(0xffffffffu, v, 1);
                    a2[f][o] = v;
                }
            if (lane == 0) {
                #pragma unroll
                for (int f = 0; f < F_STEPS; ++f) {
                    sm[RED_OFF + (node * 4 + w4) * 24 + f * 2 + 0] = a2[f][0];
                    sm[RED_OFF + (node * 4 + w4) * 24 + f * 2 + 1] = a2[f][1];
                }
            }
        }
    }
    __syncthreads();

    if (tid < nm * (F_STEPS * OUT_DIM)) {
        const int node = tid / 24;
        const int fo   = tid - node * 24;
        float ssum = sm[RED_OFF + (node * 4 + 0) * 24 + fo]
                   + sm[RED_OFF + (node * 4 + 1) * 24 + fo]
                   + sm[RED_OFF + (node * 4 + 2) * 24 + fo]
                   + sm[RED_OFF + (node * 4 + 3) * 24 + fo];
        ssum += b2[expert * OUT_DIM + (fo & 1)];
        out[(size_t)d_perm[nbase + node] * (F_STEPS * OUT_DIM) + fo] = ssum;
    }
}

extern "C" void kernel_launch(void* const* d_in, const int* in_sizes, int n_in,
                              void* d_out, int out_size) {
    const float* x      = (const float*)d_in[0];
    const int*   labels = (const int*)d_in[1];
    const float* W1     = (const float*)d_in[2];
    const float* b1     = (const float*)d_in[3];
    const float* W2     = (const float*)d_in[4];
    const float* b2     = (const float*)d_in[5];
    float* out = (float*)d_out;

    static bool attr_set = false;
    if (!attr_set) {
        cudaFuncSetAttribute(tcnn_grouped_kernel,
                             cudaFuncAttributeMaxDynamicSharedMemorySize, SMEM_BYTES);
        attr_set = true;
    }

    setup_kernel<<<129, 512>>>(labels, W1, W2);
    tcnn_grouped_kernel<<<MAXCTA, NTHREADS, SMEM_BYTES>>>(x, b1, b2, out);
}

// round 16
// speedup vs baseline: 1.0165x; 1.0165x over previous
#include <cuda_runtime.h>
#include <cstdint>

// ---- problem constants ----
#define NODES     4096
#define T_HIST    24
#define D_SKIP    256
#define E_END     128
#define KW        13
#define F_STEPS   12
#define OUT_DIM   2
#define NPB       5
#define NTHREADS  512
#define PERSIST   296        // 148 SMs x 2 CTAs

// ---- smem layout (floats), occupancy-2 budget ----
// mainloop: xb 2 bufs x [128][68] @0 (quarters; converted in place; ends 17408)
//           w1s 2 bufs x 4096 (fragment-order chunk) @17408 (ends 25600)
// stage 2 : hs [120][129] @0 (ends 15479), w2s [13][256] pairs @15480 (ends 18808), red @18808
#define XB_OFF     0
#define XB_BUF     8704
#define XB_STRIDE  68
#define W1S_OFF    17408
#define W1S_BUF    4096
#define HS_OFF     0
#define HS_STRIDE  129
#define W2S_OFF    15480
#define RED_OFF    18808
#define SMEM_FLOATS 25600
#define SMEM_BYTES  (SMEM_FLOATS * 4)

// ---- device scratch ----
__device__ int d_perm[NODES];
__device__ int d_cta_expert[1024];
__device__ int d_cta_base[1024];
__device__ int d_cta_cnt[1024];
__device__ int d_num_ctas;
// W1 fragment order for 512-thread map:
// [ex][chunk c (8)][fragpos=kt*2+mt (8)][wq (4)][lane (32)][j (4)], tf32
__device__ float d_w1f[8 * E_END * D_SKIP];
__device__ float d_w2t[8 * KW * E_END * OUT_DIM]; // [ex][kk][e][o] pairs

__device__ __forceinline__ float tf32_rna(float x) {
    unsigned u;
    asm("cvt.rna.tf32.f32 %0, %1;" : "=r"(u) : "f"(x));
    return __uint_as_float(u);
}
__device__ __forceinline__ void cp16(uint32_t dst, const float* src) {
    asm volatile("cp.async.ca.shared.global [%0], [%1], 16;" :: "r"(dst), "l"(src));
}
__device__ __forceinline__ void mma_tf32(float (&d)[4], const unsigned (&a)[4],
                                         unsigned b0, unsigned b1) {
    asm volatile(
        "mma.sync.aligned.m16n8k8.row.col.f32.tf32.tf32.f32 "
        "{%0,%1,%2,%3}, {%4,%5,%6,%7}, {%8,%9}, {%0,%1,%2,%3};"
        : "+f"(d[0]), "+f"(d[1]), "+f"(d[2]), "+f"(d[3])
        : "r"(a[0]), "r"(a[1]), "r"(a[2]), "r"(a[3]), "r"(b0), "r"(b1));
}
// packed f32x2 ops (sm_100 PTX 8.6)
__device__ __forceinline__ void fma_x2(unsigned long long& d, unsigned long long a,
                                       unsigned long long b) {
    asm("fma.rn.f32x2 %0, %1, %2, %0;" : "+l"(d) : "l"(a), "l"(b));
}
__device__ __forceinline__ void add_x2(unsigned long long& d, unsigned long long a,
                                       unsigned long long b) {
    asm("add.rn.f32x2 %0, %1, %2;" : "=l"(d) : "l"(a), "l"(b));
}
__device__ __forceinline__ unsigned long long pack_x2(float lo, float hi) {
    unsigned long long v;
    asm("mov.b64 %0, {%1, %2};" : "=l"(v) : "f"(lo), "f"(hi));
    return v;
}

// ================= setup: block 0 = prepass, blocks 1.. = weight convert =================
__global__ void setup_kernel(const int* __restrict__ labels,
                             const float* __restrict__ W1,
                             const float* __restrict__ W2) {
    const int nt = blockDim.x;
    if (blockIdx.x == 0) {
        __shared__ int cnt[8], off[8], pos[8], blkoff[9], total_s;
        const int tid = threadIdx.x;
        const int lane = tid & 31;
        if (tid < 8) { cnt[tid] = 0; pos[tid] = 0; }
        __syncthreads();
        for (int i = tid; i < NODES; i += nt) {
            int l = labels[i];
            unsigned mask = __match_any_sync(0xffffffffu, l);
            int leader = __ffs(mask) - 1;
            if (lane == leader) atomicAdd(&cnt[l], __popc(mask));
        }
        __syncthreads();
        if (tid == 0) {
            int acc = 0, bacc = 0;
            for (int e = 0; e < 8; ++e) {
                off[e] = acc;
                blkoff[e] = bacc;
                acc += cnt[e];
                bacc += (cnt[e] + NPB - 1) / NPB;
            }
            blkoff[8] = bacc;
            total_s = bacc;
            d_num_ctas = bacc;
        }
        __syncthreads();
        for (int i = tid; i < NODES; i += nt) {
            int l = labels[i];
            unsigned mask = __match_any_sync(0xffffffffu, l);
            int leader = __ffs(mask) - 1;
            int rank = __popc(mask & ((1u << lane) - 1u));
            int basep = 0;
            if (lane == leader) basep = atomicAdd(&pos[l], __popc(mask));
            basep = __shfl_sync(0xffffffffu, basep, leader);
            d_perm[off[l] + basep + rank] = i;
        }
        const int total = total_s;
        for (int i = tid; i < total; i += nt) {
            int e = 0;
            while (blkoff[e + 1] <= i) ++e;
            int j = i - blkoff[e];
            int rem = cnt[e] - j * NPB;
            d_cta_expert[i] = e;
            d_cta_base[i]   = off[e] + j * NPB;
            d_cta_cnt[i]    = rem < NPB ? rem : NPB;
        }
    } else {
        const int idx = (blockIdx.x - 1) * nt + threadIdx.x;
        const int stride = (gridDim.x - 1) * nt;
        // W1 -> fragment-order tf32 (512-thread map)
        for (int i = idx; i < 8 * E_END * D_SKIP; i += stride) {
            int ex = i >> 15;
            int r  = i & 32767;
            int c  = r >> 12;
            int r2 = r & 4095;
            int fragpos = r2 >> 9;          // kt*2 + mt
            int wq  = (r2 >> 7) & 3;
            int lane2 = (r2 >> 2) & 31;
            int j   = r2 & 3;
            int kt = fragpos >> 1, mt = fragpos & 1;
            int g = lane2 >> 2, tig = lane2 & 3;
            int e = wq * 32 + mt * 16 + g + (j & 1) * 8;
            int k = c * 32 + kt * 8 + tig + (j >> 1) * 4;
            d_w1f[i] = tf32_rna(W1[(ex * E_END + e) * D_SKIP + k]);
        }
        // W2 -> [ex][kk][e][o]
        for (int i = idx; i < 8 * KW * E_END * OUT_DIM; i += stride) {
            int ex = i / (KW * E_END * OUT_DIM);
            int r  = i - ex * (KW * E_END * OUT_DIM);
            int kk = r >> 8;
            int eo = r & 255;
            int en = eo >> 1;
            int o  = eo & 1;
            d_w2t[i] = W2[((ex * OUT_DIM + o) * E_END + en) * KW + kk];
        }
    }
}

// ================= main kernel (persistent) =================
__global__ void __launch_bounds__(NTHREADS, 2)
tcnn_grouped_kernel(const float* __restrict__ x,
                    const float* __restrict__ b1,
                    const float* __restrict__ b2,
                    float* __restrict__ out)
{
    extern __shared__ __align__(16) float sm[];
    const int num_items = d_num_ctas;

    const int tid  = threadIdx.x;
    const int warp = tid >> 5;       // 0..15
    const int lane = tid & 31;
    const int g    = lane >> 2;
    const int tig  = lane & 3;
    const int wq   = warp & 3;       // 0..3 : e-quarter
    const int wn   = warp >> 2;      // 0..3 : row-quarter
    const uint32_t smem_saddr = (uint32_t)__cvta_generic_to_shared(sm);
    const int aoff = wq * 32 + lane;

    #pragma unroll 1
    for (int item = blockIdx.x; item < num_items; item += PERSIST) {

    const int expert = d_cta_expert[item];
    const int nbase  = d_cta_base[item];
    const int nm     = d_cta_cnt[item];

    // per-node x base pointers
    const float* pxn[NPB];
    #pragma unroll
    for (int s = 0; s < NPB; ++s) {
        int node = (s < nm) ? d_perm[nbase + s] : d_perm[nbase];
        pxn[s] = x + (size_t)node * (T_HIST * D_SKIP);
    }
    const int xcount = nm * 384;      // cp16 ops per quarter

    // ---- issue xs quarter 0 into xbuf 0 ----
    #pragma unroll 1
    for (int i = tid; i < xcount; i += NTHREADS) {
        int s = i / 384;
        int r = i - s * 384;
        int t = r >> 4;
        int qd = r & 15;
        cp16(smem_saddr + (((s * 24 + t) * XB_STRIDE + qd * 4) << 2),
             pxn[s] + t * D_SKIP + qd * 4);
    }
    asm volatile("cp.async.commit_group;");

    // ---- W1 fragment-order prefetch (register double-buffer) ----
    const float4* w1src4 = (const float4*)(d_w1f + (size_t)expert * (E_END * D_SKIP));
    float4* w1dst4base = (float4*)(sm + W1S_OFF);

    float4 pre[2];
    #pragma unroll
    for (int j = 0; j < 2; ++j)
        pre[j] = w1src4[tid + 512 * j];

    float acc[2][4][4];
    #pragma unroll
    for (int mt = 0; mt < 2; ++mt)
        #pragma unroll
        for (int nt = 0; nt < 4; ++nt)
            #pragma unroll
            for (int i = 0; i < 4; ++i) acc[mt][nt][i] = 0.f;

    #pragma unroll 1
    for (int c = 0; c < 8; ++c) {
        const int buf = c & 1;
        float* xbuf = sm + XB_OFF + ((c >> 1) & 1) * XB_BUF;

        // convert quarter (c==0: q0; c odd <7: q=(c+1)/2); own elements only
        if (c == 0 || ((c & 1) && c < 7)) {
            asm volatile("cp.async.wait_group 0;");
            float* cbuf = sm + XB_OFF + (((c + 1) >> 1) & 1) * XB_BUF;
            #pragma unroll 1
            for (int i = tid; i < xcount; i += NTHREADS) {
                int s = i / 384;
                int r = i - s * 384;
                int t = r >> 4;
                int qd = r & 15;
                float4* p = (float4*)(cbuf + (s * 24 + t) * XB_STRIDE + qd * 4);
                float4 v = *p;
                v.x = tf32_rna(fmaxf(v.x, 0.f));
                v.y = tf32_rna(fmaxf(v.y, 0.f));
                v.z = tf32_rna(fmaxf(v.z, 0.f));
                v.w = tf32_rna(fmaxf(v.w, 0.f));
                *p = v;
            }
        }

        // STS prefetched W1 chunk c
        {
            float4* dst = w1dst4base + buf * (W1S_BUF / 4);
            #pragma unroll
            for (int j = 0; j < 2; ++j)
                dst[tid + 512 * j] = pre[j];
        }
        if (c < 7) {
            const float4* src = w1src4 + (c + 1) * (W1S_BUF / 4);
            #pragma unroll
            for (int j = 0; j < 2; ++j)
                pre[j] = src[tid + 512 * j];
        }
        __syncthreads();   // w1s chunk c + converted quarter visible; prev mma done

        // issue xs quarter q+1 (post-barrier)
        if ((c & 1) == 0 && c < 6) {
            const int qn = (c >> 1) + 1;
            const uint32_t dstb = smem_saddr + (qn & 1) * (XB_BUF * 4);
            const int kb4 = qn * 64;
            #pragma unroll 1
            for (int i = tid; i < xcount; i += NTHREADS) {
                int s = i / 384;
                int r = i - s * 384;
                int t = r >> 4;
                int qd = r & 15;
                cp16(dstb + (((s * 24 + t) * XB_STRIDE + qd * 4) << 2),
                     pxn[s] + kb4 + t * D_SKIP + qd * 4);
            }
            asm volatile("cp.async.commit_group;");
        }

        const float4* w1b4 = (const float4*)(sm + W1S_OFF + buf * W1S_BUF);
        #pragma unroll
        for (int kt = 0; kt < 4; ++kt) {
            const int xk = (c & 1) * 32 + kt * 8;
            unsigned a[2][4];
            #pragma unroll
            for (int mt = 0; mt < 2; ++mt) {
                float4 av = w1b4[(kt * 2 + mt) * 128 + aoff];
                a[mt][0] = __float_as_uint(av.x);
                a[mt][1] = __float_as_uint(av.y);
                a[mt][2] = __float_as_uint(av.z);
                a[mt][3] = __float_as_uint(av.w);
            }
            #pragma unroll
            for (int nt = 0; nt < 4; ++nt) {
                const int col = wn * 32 + nt * 8 + g;
                unsigned b0  = __float_as_uint(xbuf[col * XB_STRIDE + xk + tig]);
                unsigned b1v = __float_as_uint(xbuf[col * XB_STRIDE + xk + tig + 4]);
                #pragma unroll
                for (int mt = 0; mt < 2; ++mt)
                    mma_tf32(acc[mt][nt], a[mt], b0, b1v);
            }
        }
    }

    __syncthreads();   // all xb/w1s reads done -> reuse as hs[row][e]

    // ---- stage-2 weights: contiguous copy, layout [kk][e][o] ----
    {
        const float4* w2g = (const float4*)(d_w2t + expert * (KW * E_END * OUT_DIM));
        float4* w2s = (float4*)(sm + W2S_OFF);
        #pragma unroll 1
        for (int i = tid; i < KW * E_END * OUT_DIM / 4; i += NTHREADS)
            w2s[i] = w2g[i];
    }

    // ---- epilogue: hs[row][e] = relu(D[e][row] + b1[e]) ----
    {
        const float* b1g = b1 + expert * E_END;
        const int maxrow = nm * T_HIST;
        #pragma unroll
        for (int mt = 0; mt < 2; ++mt) {
            const int eA = wq * 32 + mt * 16 + g;
            const int eB = eA + 8;
            const float bA = b1g[eA];
            const float bB = b1g[eB];
            #pragma unroll
            for (int nt = 0; nt < 4; ++nt) {
                const int row0 = wn * 32 + nt * 8 + 2 * tig;
                if (row0 < maxrow) {
                    sm[HS_OFF + row0 * HS_STRIDE + eA] = fmaxf(acc[mt][nt][0] + bA, 0.f);
                    sm[HS_OFF + row0 * HS_STRIDE + eB] = fmaxf(acc[mt][nt][2] + bB, 0.f);
                }
                const int row1 = row0 + 1;
                if (row1 < maxrow) {
                    sm[HS_OFF + row1 * HS_STRIDE + eA] = fmaxf(acc[mt][nt][1] + bA, 0.f);
                    sm[HS_OFF + row1 * HS_STRIDE + eB] = fmaxf(acc[mt][nt][3] + bB, 0.f);
                }
            }
        }
    }
    __syncthreads();

    // ---- stage 2: per-node temporal conv, packed f32x2 (16 warps, 2 rounds) ----
    #pragma unroll 1
    for (int iter = 0; iter < 2; ++iter) {
        const int wj   = iter * 16 + warp;
        const int node = wj >> 2;
        const int w4   = wj & 3;
        if (node < nm) {
            const int e = w4 * 32 + lane;
            // packed weight pairs (o0,o1) per kk
            unsigned long long w2p[KW];
            const unsigned long long* w2row =
                (const unsigned long long*)(sm + W2S_OFF) + e;   // + kk*128
            #pragma unroll
            for (int kk = 0; kk < KW; ++kk)
                w2p[kk] = w2row[kk * 128];

            unsigned long long a2p[F_STEPS];
            #pragma unroll
            for (int f = 0; f < F_STEPS; ++f) a2p[f] = 0ull;

            const float* hsp = sm + HS_OFF + node * T_HIST * HS_STRIDE + e;
            #pragma unroll
            for (int t = 0; t < T_HIST; ++t) {
                const float hv = hsp[t * HS_STRIDE];
                const unsigned long long hvp = pack_x2(hv, hv);
                #pragma unroll
                for (int kk = 0; kk < KW; ++kk) {
                    const int f = t - kk;
                    if (f >= 0 && f < F_STEPS)
                        fma_x2(a2p[f], hvp, w2p[kk]);
                }
            }
            #pragma unroll
            for (int f = 0; f < F_STEPS; ++f) {
                unsigned long long v = a2p[f];
                #pragma unroll
                for (int sh = 16; sh >= 1; sh >>= 1) {
                    unsigned long long o = __shfl_xor_sync(0xffffffffu, v, sh);
                    add_x2(v, v, o);
                }
                a2p[f] = v;
            }
            if (lane == 0) {
                unsigned long long* redp =
                    (unsigned long long*)(sm + RED_OFF) + (node * 4 + w4) * 12;
                #pragma unroll
                for (int f = 0; f < F_STEPS; ++f)
                    redp[f] = a2p[f];
            }
        }
    }
    __syncthreads();

    if (tid < nm * (F_STEPS * OUT_DIM)) {
        const int node = tid / 24;
        const int fo   = tid - node * 24;
        float ssum = sm[RED_OFF + (node * 4 + 0) * 24 + fo]
                   + sm[RED_OFF + (node * 4 + 1) * 24 + fo]
                   + sm[RED_OFF + (node * 4 + 2) * 24 + fo]
                   + sm[RED_OFF + (node * 4 + 3) * 24 + fo];
        ssum += b2[expert * OUT_DIM + (fo & 1)];
        out[(size_t)d_perm[nbase + node] * (F_STEPS * OUT_DIM) + fo] = ssum;
    }
    __syncthreads();   // red/hs reads done before next item's cp.async reuses region

    }  // item loop
}

extern "C" void kernel_launch(void* const* d_in, const int* in_sizes, int n_in,
                              void* d_out, int out_size) {
    const float* x      = (const float*)d_in[0];
    const int*   labels = (const int*)d_in[1];
    const float* W1     = (const float*)d_in[2];
    const float* b1     = (const float*)d_in[3];
    const float* W2     = (const float*)d_in[4];
    const float* b2     = (const float*)d_in[5];
    float* out = (float*)d_out;

    static bool attr_set = false;
    if (!attr_set) {
        cudaFuncSetAttribute(tcnn_grouped_kernel,
                             cudaFuncAttributeMaxDynamicSharedMemorySize, SMEM_BYTES);
        attr_set = true;
    }

    setup_kernel<<<129, 512>>>(labels, W1, W2);
    tcnn_grouped_kernel<<<PERSIST, NTHREADS, SMEM_BYTES>>>(x, b1, b2, out);
}